// round 12
// baseline (speedup 1.0000x reference)
#include <cuda_runtime.h>
#include <cuda_bf16.h>
#include <cuda_fp16.h>
#include <cstdint>

// Problem constants
#define Bsz 2
#define Sl  2048
#define Dm  768
#define Iw  1536
#define Nst 16
#define Rr  48
#define Ms  (Bsz * Sl)          // 4096 rows
#define TWO_I (2 * Iw)          // 3072

// ---------------------------------------------------------------------------
// Scratch (device globals)
// ---------------------------------------------------------------------------
__device__ float g_ssm [(size_t)Ms * (Rr + 2 * Nst)];
__device__ float g_dt  [(size_t)Ms * Iw];

__device__ __half g_x16   [(size_t)Ms * Dm];
__device__ __half g_w1    [(size_t)TWO_I * Dm];
__device__ __half g_hid16 [(size_t)Ms * Iw];    // pre-conv hidden (fp16)
__device__ __half g_gate16[(size_t)Ms * Iw];    // silu(gate) (fp16)
__device__ __half g_h16   [(size_t)Ms * Iw];    // post-conv h (fp16)
__device__ __half g_wx16  [(size_t)128 * Iw];   // x_proj_w padded 80->128 rows
__device__ __half g_ts16  [(size_t)Ms * 64];    // time-step part, K padded 48->64
__device__ __half g_wdt16 [(size_t)Iw * 64];    // dt_proj_w padded 48->64 cols
__device__ __half g_y16   [(size_t)Ms * Iw];
__device__ __half g_w2    [(size_t)Dm * Iw];

// ---------------------------------------------------------------------------
// Helpers
// ---------------------------------------------------------------------------
__device__ __forceinline__ uint32_t smem_u32(const void* p) {
    uint32_t a;
    asm("{ .reg .u64 t; cvta.to.shared.u64 t, %1; cvt.u32.u64 %0, t; }" : "=r"(a) : "l"(p));
    return a;
}
__device__ __forceinline__ void cp16(uint32_t saddr, const void* gsrc) {
    asm volatile("cp.async.cg.shared.global [%0], [%1], 16;" :: "r"(saddr), "l"(gsrc));
}
#define CP_COMMIT() asm volatile("cp.async.commit_group;" ::: "memory")
#define CP_WAIT(n)  asm volatile("cp.async.wait_group %0;" :: "n"(n) : "memory")

__device__ __forceinline__ void ldm_x4(uint32_t* r, uint32_t addr) {
    asm volatile("ldmatrix.sync.aligned.m8n8.x4.shared.b16 {%0,%1,%2,%3}, [%4];"
                 : "=r"(r[0]), "=r"(r[1]), "=r"(r[2]), "=r"(r[3]) : "r"(addr));
}
__device__ __forceinline__ void ldm_x2(uint32_t* r, uint32_t addr) {
    asm volatile("ldmatrix.sync.aligned.m8n8.x2.shared.b16 {%0,%1}, [%2];"
                 : "=r"(r[0]), "=r"(r[1]) : "r"(addr));
}
__device__ __forceinline__ void mma16816(float* c, const uint32_t* a, const uint32_t* b) {
    asm volatile("mma.sync.aligned.m16n8k16.row.col.f32.f16.f16.f32 "
                 "{%0,%1,%2,%3}, {%4,%5,%6,%7}, {%8,%9}, {%0,%1,%2,%3};"
                 : "+f"(c[0]), "+f"(c[1]), "+f"(c[2]), "+f"(c[3])
                 : "r"(a[0]), "r"(a[1]), "r"(a[2]), "r"(a[3]), "r"(b[0]), "r"(b[1]));
}
__device__ __forceinline__ float fast_silu(float v) {
    return v * __fdividef(1.f, 1.f + __expf(-v));
}

// ---------------------------------------------------------------------------
// HMMA fp16 GEMM with fused epilogues. Template <BM, BN, EPI>.
// EPI 0: plain fp32 store
// EPI 1: x_proj  — fp32 ssm (cols < Nstore) + fp16 ts16 (bn==0, col<48, pad 0)
// EPI 2: dt_proj — softplus(acc + bias), alpha on last timestep, fp32 store
// EPI 3: in_proj — cols < Iw -> fp16 aux (hidden); cols >= Iw -> silu -> fp16 aux2
// ---------------------------------------------------------------------------
#define STRD 40

template<int BM, int BN, int EPI>
__global__ __launch_bounds__(256, (BM == 64 ? 3 : 2))
void hmma_f16(const __half* __restrict__ A16, const __half* __restrict__ W16,
              float* __restrict__ C, int M, int K, int ldC, int Nstore,
              const float* __restrict__ bias, const float* __restrict__ lastscale,
              __half* __restrict__ aux, __half* __restrict__ aux2)
{
    constexpr int NWN = BN / 32;            // warps along n
    constexpr int NWM = 8 / NWN;            // warps along m
    constexpr int MT  = BM / (NWM * 16);    // 16-row m-tiles per warp
    constexpr int A_TILE = BM * STRD * 2;
    constexpr int W_TILE = BN * STRD * 2;
    constexpr int STAGE = A_TILE + W_TILE;
    constexpr int NSLOT = (BM + BN) * 4;    // 16B slots per stage

    extern __shared__ __align__(16) char smem[];
    const uint32_t sb = smem_u32(smem);
    const int tid = threadIdx.x;
    const int wid = tid >> 5, lane = tid & 31;
    const int warp_m = wid / NWN, warp_n = wid % NWN;
    const int bm = blockIdx.y * BM, bn = blockIdx.x * BN;

    auto load_stage = [&](int st, int k0) {
#pragma unroll
        for (int v = tid; v < NSLOT; v += 256) {
            int row, c16;
            const __half* src;
            uint32_t base;
            if (v < BM * 4) {
                row = v >> 2; c16 = v & 3;
                src = A16 + (size_t)(bm + row) * K + k0 + c16 * 8;
                base = 0;
            } else {
                int u = v - BM * 4;
                row = u >> 2; c16 = u & 3;
                src = W16 + (size_t)(bn + row) * K + k0 + c16 * 8;
                base = A_TILE;
            }
            cp16(sb + st * STAGE + base + (row * STRD + c16 * 8) * 2, src);
        }
        CP_COMMIT();
    };

    float acc[MT][4][4];
#pragma unroll
    for (int i = 0; i < MT; i++)
#pragma unroll
        for (int j = 0; j < 4; j++)
#pragma unroll
            for (int k = 0; k < 4; k++) acc[i][j][k] = 0.f;

    const int nch = K >> 5;
    load_stage(0, 0);
    if (nch > 1) load_stage(1, 32);

    const int a_r = warp_m * (MT * 16) + (lane & 15);
    const int a_k = (lane >> 4) * 8;
    const int b_r = warp_n * 32 + (lane & 7);
    const int b_k = ((lane >> 3) & 1) * 8;

    for (int ch = 0; ch < nch; ch++) {
        const int st = ch % 3;
        if (ch == nch - 1) { CP_WAIT(0); } else { CP_WAIT(1); }
        __syncthreads();
        if (ch + 2 < nch) load_stage((ch + 2) % 3, (ch + 2) << 5);

        const uint32_t aB = sb + st * STAGE;
        const uint32_t wB = aB + A_TILE;

#pragma unroll
        for (int kk = 0; kk < 2; kk++) {
            uint32_t a[MT][4], b[4][2];
#pragma unroll
            for (int mt = 0; mt < MT; mt++)
                ldm_x4(a[mt], aB + ((a_r + mt * 16) * STRD + a_k + kk * 16) * 2);
#pragma unroll
            for (int nt = 0; nt < 4; nt++)
                ldm_x2(b[nt], wB + ((b_r + nt * 8) * STRD + b_k + kk * 16) * 2);
#pragma unroll
            for (int mt = 0; mt < MT; mt++)
#pragma unroll
                for (int nt = 0; nt < 4; nt++)
                    mma16816(acc[mt][nt], a[mt], b[nt]);
        }
    }

    const int er = bm + warp_m * (MT * 16) + (lane >> 2);
    const int ec = bn + warp_n * 32 + (lane & 3) * 2;
#pragma unroll
    for (int mt = 0; mt < MT; mt++)
#pragma unroll
        for (int nt = 0; nt < 4; nt++) {
            int r0 = er + mt * 16;
            int r1 = r0 + 8;
            int c = ec + nt * 8;
            float* ac = acc[mt][nt];
            if (EPI == 0) {
                *(float2*)&C[(size_t)r0 * ldC + c] = make_float2(ac[0], ac[1]);
                *(float2*)&C[(size_t)r1 * ldC + c] = make_float2(ac[2], ac[3]);
            } else if (EPI == 1) {
                if (c < Nstore) {
                    *(float2*)&C[(size_t)r0 * ldC + c] = make_float2(ac[0], ac[1]);
                    *(float2*)&C[(size_t)r1 * ldC + c] = make_float2(ac[2], ac[3]);
                }
                if (blockIdx.x == 0) {   // c < 64; pad cols >= 48 with zero
                    __half2 z = __half2(__half(0.f), __half(0.f));
                    __half2 h0 = (c < Rr) ? __floats2half2_rn(ac[0], ac[1]) : z;
                    __half2 h1 = (c < Rr) ? __floats2half2_rn(ac[2], ac[3]) : z;
                    *(__half2*)&aux[(size_t)r0 * 64 + c] = h0;
                    *(__half2*)&aux[(size_t)r1 * 64 + c] = h1;
                }
            } else if (EPI == 2) {
                float u[4] = {ac[0], ac[1], ac[2], ac[3]};
#pragma unroll
                for (int e = 0; e < 4; e++) {
                    int col = c + (e & 1);
                    int row = (e < 2) ? r0 : r1;
                    float v = u[e] + bias[col];
                    v = (v > 15.f) ? v : __logf(1.f + __expf(v));
                    if ((row & (Sl - 1)) == Sl - 1) v *= lastscale[col];
                    u[e] = v;
                }
                *(float2*)&C[(size_t)r0 * ldC + c] = make_float2(u[0], u[1]);
                *(float2*)&C[(size_t)r1 * ldC + c] = make_float2(u[2], u[3]);
            } else {  // EPI == 3
                if (c < Iw) {
                    *(__half2*)&aux[(size_t)r0 * Iw + c] = __floats2half2_rn(ac[0], ac[1]);
                    *(__half2*)&aux[(size_t)r1 * Iw + c] = __floats2half2_rn(ac[2], ac[3]);
                } else {
                    int cg = c - Iw;
                    *(__half2*)&aux2[(size_t)r0 * Iw + cg] =
                        __floats2half2_rn(fast_silu(ac[0]), fast_silu(ac[1]));
                    *(__half2*)&aux2[(size_t)r1 * Iw + cg] =
                        __floats2half2_rn(fast_silu(ac[2]), fast_silu(ac[3]));
                }
            }
        }
}

// ---------------------------------------------------------------------------
// Fused prep: all fp32->fp16 conversions in one launch.
// ---------------------------------------------------------------------------
#define PN0 ((Ms * Dm) / 4)
#define PN1 ((TWO_I * Dm) / 4)
#define PN2 ((Dm * Iw) / 4)
#define PN3 ((128 * Iw) / 4)
#define PN4 ((Iw * 64) / 4)
#define PTOT (PN0 + PN1 + PN2 + PN3 + PN4)

__global__ __launch_bounds__(256)
void prep_f16(const float* __restrict__ x, const float* __restrict__ w1f,
              const float* __restrict__ w2f, const float* __restrict__ wxf,
              const float* __restrict__ wdtf,
              __half* __restrict__ x16, __half* __restrict__ w1,
              __half* __restrict__ w2, __half* __restrict__ wx16,
              __half* __restrict__ wdt16)
{
    int i = blockIdx.x * 256 + threadIdx.x;
    if (i >= PTOT) return;
    const float* src;
    __half* dst;
    long j;
    long srcoff;
    bool zero = false;
    if (i < PN0) { j = i; srcoff = j * 4; src = x; dst = x16; }
    else if (i < PN0 + PN1) { j = i - PN0; srcoff = j * 4; src = w1f; dst = w1; }
    else if (i < PN0 + PN1 + PN2) { j = i - PN0 - PN1; srcoff = j * 4; src = w2f; dst = w2; }
    else if (i < PN0 + PN1 + PN2 + PN3) {
        j = i - PN0 - PN1 - PN2; srcoff = j * 4; src = wxf; dst = wx16;
        zero = ((j * 4) / Iw) >= (Rr + 2 * Nst);
    } else {
        j = i - PN0 - PN1 - PN2 - PN3; src = wdtf; dst = wdt16;
        long col4 = j & 15, row = j >> 4;
        zero = (col4 >= 12);
        srcoff = row * Rr + col4 * 4;
    }
    __half2* op = (__half2*)(dst + j * 4);
    if (zero) {
        op[0] = __half2(__half(0.f), __half(0.f));
        op[1] = __half2(__half(0.f), __half(0.f));
    } else {
        float4 v = *(const float4*)(src + srcoff);
        op[0] = __floats2half2_rn(v.x, v.y);
        op[1] = __floats2half2_rn(v.z, v.w);
    }
}

// ---------------------------------------------------------------------------
// Causal depthwise conv1d (K=4) + bias + SiLU — half2 rolling window.
// ---------------------------------------------------------------------------
__global__ __launch_bounds__(256)
void conv_silu3(const __half* __restrict__ hid,
                const float* __restrict__ cw,
                const float* __restrict__ cb,
                __half* __restrict__ h16)
{
    const int blk = blockIdx.x;                 // Bsz * (Sl/16)
    const int b = blk / (Sl / 16);
    const int st = (blk % (Sl / 16)) * 16;
    const int rs = Iw / 2;                      // half2 row stride

#pragma unroll 1
    for (int ic = 0; ic < Iw / 512; ic++) {
        const int p = ic * 256 + threadIdx.x;   // channel pair 0..767
        const int i = p * 2;
        float4 wa = *(const float4*)(cw + (size_t)i * 4);
        float4 wb = *(const float4*)(cw + (size_t)(i + 1) * 4);
        float bx = cb[i], by = cb[i + 1];
        const __half2* base = (const __half2*)(hid + ((size_t)b * Sl + st) * Iw) + p;
        __half2* outp = (__half2*)(h16 + ((size_t)b * Sl + st) * Iw) + p;

        float2 x3, x2, x1;
        if (st > 0) {
            x3 = __half22float2(base[-3 * rs]);
            x2 = __half22float2(base[-2 * rs]);
            x1 = __half22float2(base[-1 * rs]);
        } else {
            x3 = make_float2(0.f, 0.f); x2 = x3; x1 = x3;
        }
#pragma unroll
        for (int s = 0; s < 16; s++) {
            float2 x0 = __half22float2(base[(size_t)s * rs]);
            float ax = fmaf(wa.w, x0.x, fmaf(wa.z, x1.x, fmaf(wa.y, x2.x, fmaf(wa.x, x3.x, bx))));
            float ay = fmaf(wb.w, x0.y, fmaf(wb.z, x1.y, fmaf(wb.y, x2.y, fmaf(wb.x, x3.y, by))));
            ax = fast_silu(ax);
            ay = fast_silu(ay);
            outp[(size_t)s * rs] = __floats2half2_rn(ax, ay);
            x3 = x2; x2 = x1; x1 = x0;
        }
    }
}

// ---------------------------------------------------------------------------
// Selective scan v5: 2 states/lane, 8 lanes/channel, 16 ch/block, 128 threads.
// gate already silu'd, fp16.
// ---------------------------------------------------------------------------
#define SCT 64
#define NCHK (Sl / SCT)

__global__ __launch_bounds__(128)
void scan_kernel5(const float* __restrict__ dt,
                  const __half* __restrict__ h16,
                  const float* __restrict__ ssm,
                  const __half* __restrict__ gate16,
                  const float* __restrict__ A_log,
                  const float* __restrict__ Dv,
                  const float* __restrict__ fg,
                  __half* __restrict__ y16)
{
    __shared__ __align__(16) float  s_dt[2][SCT][16];
    __shared__ __align__(16) float  s_B [2][SCT][16];
    __shared__ __align__(16) float  s_C [2][SCT][16];
    __shared__ __align__(16) __half s_h [2][SCT][16];
    __shared__ __align__(16) __half s_g [2][SCT][16];
    __shared__ __align__(16) float  s_y [SCT][16];
    __shared__ float s_D[16];

    const int tid = threadIdx.x;                // 0..127
    const int blk = blockIdx.x;                 // 0..191
    const int b = blk / (Iw / 16);
    const int i0 = (blk % (Iw / 16)) * 16;

    const int wid = tid >> 5;                   // 0..3
    const int lane = tid & 31;
    const int ci = wid * 4 + (lane >> 3);       // channel 0..15
    const int sl = lane & 7;                    // 2 states: sl*2, sl*2+1

    if (tid < 16) s_D[tid] = Dv[i0 + tid];

    float An0 = -__expf(A_log[(size_t)(i0 + ci) * Nst + sl * 2]);
    float An1 = -__expf(A_log[(size_t)(i0 + ci) * Nst + sl * 2 + 1]);
    float st0 = 0.f, st1 = 0.f;

    const size_t row0 = (size_t)b * Sl;

    const uint32_t a_dt = smem_u32(&s_dt[0][0][0]);
    const uint32_t a_B  = smem_u32(&s_B [0][0][0]);
    const uint32_t a_C  = smem_u32(&s_C [0][0][0]);
    const uint32_t a_h  = smem_u32(&s_h [0][0][0]);
    const uint32_t a_g  = smem_u32(&s_g [0][0][0]);
    const uint32_t stoff  = SCT * 16 * 4;
    const uint32_t stoffh = SCT * 16 * 2;

    auto issue = [&](int st, int s0) {
#pragma unroll
        for (int l = 0; l < 2; l++) {
            int v = tid + l * 128;
            int r = v >> 2, c4 = (v & 3) * 4;
            size_t grow = row0 + s0 + r;
            uint32_t off = st * stoff + (r * 16 + c4) * 4;
            cp16(a_dt + off, dt  + grow * Iw + i0 + c4);
            cp16(a_B  + off, ssm + grow * (Rr + 2 * Nst) + Rr + c4);
            cp16(a_C  + off, ssm + grow * (Rr + 2 * Nst) + Rr + Nst + c4);
        }
        {
            int v = tid;
            int r = v >> 1, c8 = (v & 1) * 8;
            size_t grow = row0 + s0 + r;
            uint32_t offh = st * stoffh + (r * 16 + c8) * 2;
            cp16(a_h + offh, h16    + grow * Iw + i0 + c8);
            cp16(a_g + offh, gate16 + grow * Iw + i0 + c8);
        }
        CP_COMMIT();
    };

    issue(0, 0);

    for (int ch = 0; ch < NCHK; ch++) {
        const int st = ch & 1;
        const int s0 = ch * SCT;
        if (ch + 1 < NCHK) { issue(st ^ 1, s0 + SCT); CP_WAIT(1); }
        else               { CP_WAIT(0); }
        __syncthreads();

#pragma unroll 4
        for (int s = 0; s < SCT; s++) {
            float dtv = s_dt[st][s][ci];
            float hv  = __half2float(s_h[st][s][ci]);
            float2 Bv = *(const float2*)&s_B[st][s][sl * 2];
            float2 Cv = *(const float2*)&s_C[st][s][sl * 2];
            float dth = dtv * hv;
            st0 = fmaf(__expf(An0 * dtv), st0, dth * Bv.x);
            st1 = fmaf(__expf(An1 * dtv), st1, dth * Bv.y);
            float part = st0 * Cv.x + st1 * Cv.y;
            part += __shfl_xor_sync(0xffffffffu, part, 4);
            part += __shfl_xor_sync(0xffffffffu, part, 2);
            part += __shfl_xor_sync(0xffffffffu, part, 1);
            if (sl == 0) s_y[s][ci] = part;
        }
        __syncthreads();

#pragma unroll
        for (int k = 0; k < 8; k++) {
            int idx = tid + k * 128;
            int r = idx >> 4, c = idx & 15;
            float hv = __half2float(s_h[st][r][c]);
            float sg = __half2float(s_g[st][r][c]);
            float val = (s_y[r][c] + hv * s_D[c]) * sg;
            if (s0 + r == Sl - 1) val *= fg[i0 + c];
            y16[(row0 + s0 + r) * Iw + i0 + c] = __float2half_rn(val);
        }
        __syncthreads();
    }
}

// ---------------------------------------------------------------------------
// Launch
// ---------------------------------------------------------------------------
extern "C" void kernel_launch(void* const* d_in, const int* in_sizes, int n_in,
                              void* d_out, int out_size)
{
    const float* x          = (const float*)d_in[0];
    const float* in_proj_w  = (const float*)d_in[1];
    const float* conv_w     = (const float*)d_in[2];
    const float* conv_b     = (const float*)d_in[3];
    const float* x_proj_w   = (const float*)d_in[4];
    const float* dt_proj_w  = (const float*)d_in[5];
    const float* dt_proj_b  = (const float*)d_in[6];
    const float* A_log      = (const float*)d_in[7];
    const float* Dv         = (const float*)d_in[8];
    const float* out_proj_w = (const float*)d_in[9];
    const float* alpha      = (const float*)d_in[10];
    const float* fg         = (const float*)d_in[11];
    float* out = (float*)d_out;

    float *ssm, *dt;
    cudaGetSymbolAddress((void**)&ssm, g_ssm);
    cudaGetSymbolAddress((void**)&dt,  g_dt);

    __half *x16, *w1, *hid16, *gate16, *h16, *wx16, *ts16, *wdt16, *y16, *w2;
    cudaGetSymbolAddress((void**)&x16,    g_x16);
    cudaGetSymbolAddress((void**)&w1,     g_w1);
    cudaGetSymbolAddress((void**)&hid16,  g_hid16);
    cudaGetSymbolAddress((void**)&gate16, g_gate16);
    cudaGetSymbolAddress((void**)&h16,    g_h16);
    cudaGetSymbolAddress((void**)&wx16,   g_wx16);
    cudaGetSymbolAddress((void**)&ts16,   g_ts16);
    cudaGetSymbolAddress((void**)&wdt16,  g_wdt16);
    cudaGetSymbolAddress((void**)&y16,    g_y16);
    cudaGetSymbolAddress((void**)&w2,     g_w2);

    constexpr int SMEM_BIG   = 3 * (128 + 128) * STRD * 2;   // 61440
    constexpr int SMEM_SMALL = 3 * (64 + 64) * STRD * 2;     // 30720
    cudaFuncSetAttribute(hmma_f16<128,128,3>, cudaFuncAttributeMaxDynamicSharedMemorySize, SMEM_BIG);
    cudaFuncSetAttribute(hmma_f16<64,64,1>,   cudaFuncAttributeMaxDynamicSharedMemorySize, SMEM_SMALL);
    cudaFuncSetAttribute(hmma_f16<64,64,2>,   cudaFuncAttributeMaxDynamicSharedMemorySize, SMEM_SMALL);
    cudaFuncSetAttribute(hmma_f16<64,64,0>,   cudaFuncAttributeMaxDynamicSharedMemorySize, SMEM_SMALL);

    // 0) all fp16 conversions in one launch
    prep_f16<<<(PTOT + 255) / 256, 256>>>(x, in_proj_w, out_proj_w, x_proj_w,
                                          dt_proj_w, x16, w1, w2, wx16, wdt16);

    // 1) in_proj (EPI=3): hidden -> hid16, silu(gate) -> gate16
    hmma_f16<128,128,3><<<dim3(TWO_I / 128, Ms / 128), 256, SMEM_BIG>>>(
        x16, w1, nullptr, Ms, Dm, TWO_I, TWO_I, nullptr, nullptr, hid16, gate16);

    // 2) conv + SiLU -> h16
    conv_silu3<<<Bsz * (Sl / 16), 256>>>(hid16, conv_w, conv_b, h16);

    // 3) x_proj (BM=64, EPI=1): ssm fp32 (cols<80) + ts16 fp16 padded
    hmma_f16<64,64,1><<<dim3(2, Ms / 64), 256, SMEM_SMALL>>>(
        h16, wx16, ssm, Ms, Iw, Rr + 2 * Nst, Rr + 2 * Nst, nullptr, nullptr, ts16, nullptr);

    // 4) dt_proj (BM=64, EPI=2): dt = softplus(ts16 @ wdt16^T + b), alpha on last
    hmma_f16<64,64,2><<<dim3(Iw / 64, Ms / 64), 256, SMEM_SMALL>>>(
        ts16, wdt16, dt, Ms, 64, Iw, Iw, dt_proj_b, alpha, nullptr, nullptr);

    // 5) scan v5 (reads h16/gate16, emits fp16 y)
    scan_kernel5<<<(Bsz * Iw) / 16, 128>>>(dt, h16, ssm, gate16, A_log, Dv, fg, y16);

    // 6) out_proj (BM=64, EPI=0): out[4096,768] = y16 @ w2^T
    hmma_f16<64,64,0><<<dim3(Dm / 64, Ms / 64), 256, SMEM_SMALL>>>(
        y16, w2, out, Ms, Iw, Dm, Dm, nullptr, nullptr, nullptr, nullptr);
}

// round 13
// speedup vs baseline: 1.0096x; 1.0096x over previous
#include <cuda_runtime.h>
#include <cuda_bf16.h>
#include <cuda_fp16.h>
#include <cstdint>

// Problem constants
#define Bsz 2
#define Sl  2048
#define Dm  768
#define Iw  1536
#define Nst 16
#define Rr  48
#define Ms  (Bsz * Sl)          // 4096 rows
#define TWO_I (2 * Iw)          // 3072

// ---------------------------------------------------------------------------
// Scratch (device globals)
// ---------------------------------------------------------------------------
__device__ float g_ssm [(size_t)Ms * (Rr + 2 * Nst)];

__device__ __half g_x16   [(size_t)Ms * Dm];
__device__ __half g_w1    [(size_t)TWO_I * Dm];
__device__ __half g_hid16 [(size_t)Ms * Iw];    // pre-conv hidden (fp16)
__device__ __half g_gate16[(size_t)Ms * Iw];    // silu(gate) (fp16)
__device__ __half g_h16   [(size_t)Ms * Iw];    // post-conv h (fp16)
__device__ __half g_wx16  [(size_t)128 * Iw];   // x_proj_w padded 80->128 rows
__device__ __half g_ts16  [(size_t)Ms * 64];    // time-step part, K padded 48->64
__device__ __half g_wdt16 [(size_t)Iw * 64];    // dt_proj_w padded 48->64 cols
__device__ __half g_dt16  [(size_t)Ms * Iw];    // softplus dt (fp16)
__device__ __half g_y16   [(size_t)Ms * Iw];
__device__ __half g_w2    [(size_t)Dm * Iw];

// ---------------------------------------------------------------------------
// Helpers
// ---------------------------------------------------------------------------
__device__ __forceinline__ uint32_t smem_u32(const void* p) {
    uint32_t a;
    asm("{ .reg .u64 t; cvta.to.shared.u64 t, %1; cvt.u32.u64 %0, t; }" : "=r"(a) : "l"(p));
    return a;
}
__device__ __forceinline__ void cp16(uint32_t saddr, const void* gsrc) {
    asm volatile("cp.async.cg.shared.global [%0], [%1], 16;" :: "r"(saddr), "l"(gsrc));
}
#define CP_COMMIT() asm volatile("cp.async.commit_group;" ::: "memory")
#define CP_WAIT(n)  asm volatile("cp.async.wait_group %0;" :: "n"(n) : "memory")

__device__ __forceinline__ void ldm_x4(uint32_t* r, uint32_t addr) {
    asm volatile("ldmatrix.sync.aligned.m8n8.x4.shared.b16 {%0,%1,%2,%3}, [%4];"
                 : "=r"(r[0]), "=r"(r[1]), "=r"(r[2]), "=r"(r[3]) : "r"(addr));
}
__device__ __forceinline__ void ldm_x2(uint32_t* r, uint32_t addr) {
    asm volatile("ldmatrix.sync.aligned.m8n8.x2.shared.b16 {%0,%1}, [%2];"
                 : "=r"(r[0]), "=r"(r[1]) : "r"(addr));
}
__device__ __forceinline__ void mma16816(float* c, const uint32_t* a, const uint32_t* b) {
    asm volatile("mma.sync.aligned.m16n8k16.row.col.f32.f16.f16.f32 "
                 "{%0,%1,%2,%3}, {%4,%5,%6,%7}, {%8,%9}, {%0,%1,%2,%3};"
                 : "+f"(c[0]), "+f"(c[1]), "+f"(c[2]), "+f"(c[3])
                 : "r"(a[0]), "r"(a[1]), "r"(a[2]), "r"(a[3]), "r"(b[0]), "r"(b[1]));
}
__device__ __forceinline__ float fast_silu(float v) {
    return v * __fdividef(1.f, 1.f + __expf(-v));
}

// ---------------------------------------------------------------------------
// HMMA fp16 GEMM with fused epilogues. Template <BM, BN, EPI>.
// EPI 0: plain fp32 store
// EPI 1: x_proj  — fp32 ssm (cols < Nstore) + fp16 ts16 (bn==0, col<48, pad 0)
// EPI 2: dt_proj — softplus(acc + bias), alpha on last timestep, fp16 -> aux
// EPI 3: in_proj — cols < Iw -> fp16 aux (hidden); cols >= Iw -> silu -> fp16 aux2
// ---------------------------------------------------------------------------
#define STRD 40

template<int BM, int BN, int EPI>
__global__ __launch_bounds__(256, (BM == 64 ? 3 : 2))
void hmma_f16(const __half* __restrict__ A16, const __half* __restrict__ W16,
              float* __restrict__ C, int M, int K, int ldC, int Nstore,
              const float* __restrict__ bias, const float* __restrict__ lastscale,
              __half* __restrict__ aux, __half* __restrict__ aux2)
{
    constexpr int NWN = BN / 32;            // warps along n
    constexpr int NWM = 8 / NWN;            // warps along m
    constexpr int MT  = BM / (NWM * 16);    // 16-row m-tiles per warp
    constexpr int A_TILE = BM * STRD * 2;
    constexpr int W_TILE = BN * STRD * 2;
    constexpr int STAGE = A_TILE + W_TILE;
    constexpr int NSLOT = (BM + BN) * 4;    // 16B slots per stage

    extern __shared__ __align__(16) char smem[];
    const uint32_t sb = smem_u32(smem);
    const int tid = threadIdx.x;
    const int wid = tid >> 5, lane = tid & 31;
    const int warp_m = wid / NWN, warp_n = wid % NWN;
    const int bm = blockIdx.y * BM, bn = blockIdx.x * BN;

    auto load_stage = [&](int st, int k0) {
#pragma unroll
        for (int v = tid; v < NSLOT; v += 256) {
            int row, c16;
            const __half* src;
            uint32_t base;
            if (v < BM * 4) {
                row = v >> 2; c16 = v & 3;
                src = A16 + (size_t)(bm + row) * K + k0 + c16 * 8;
                base = 0;
            } else {
                int u = v - BM * 4;
                row = u >> 2; c16 = u & 3;
                src = W16 + (size_t)(bn + row) * K + k0 + c16 * 8;
                base = A_TILE;
            }
            cp16(sb + st * STAGE + base + (row * STRD + c16 * 8) * 2, src);
        }
        CP_COMMIT();
    };

    float acc[MT][4][4];
#pragma unroll
    for (int i = 0; i < MT; i++)
#pragma unroll
        for (int j = 0; j < 4; j++)
#pragma unroll
            for (int k = 0; k < 4; k++) acc[i][j][k] = 0.f;

    const int nch = K >> 5;
    load_stage(0, 0);
    if (nch > 1) load_stage(1, 32);

    const int a_r = warp_m * (MT * 16) + (lane & 15);
    const int a_k = (lane >> 4) * 8;
    const int b_r = warp_n * 32 + (lane & 7);
    const int b_k = ((lane >> 3) & 1) * 8;

    for (int ch = 0; ch < nch; ch++) {
        const int st = ch % 3;
        if (ch == nch - 1) { CP_WAIT(0); } else { CP_WAIT(1); }
        __syncthreads();
        if (ch + 2 < nch) load_stage((ch + 2) % 3, (ch + 2) << 5);

        const uint32_t aB = sb + st * STAGE;
        const uint32_t wB = aB + A_TILE;

#pragma unroll
        for (int kk = 0; kk < 2; kk++) {
            uint32_t a[MT][4], b[4][2];
#pragma unroll
            for (int mt = 0; mt < MT; mt++)
                ldm_x4(a[mt], aB + ((a_r + mt * 16) * STRD + a_k + kk * 16) * 2);
#pragma unroll
            for (int nt = 0; nt < 4; nt++)
                ldm_x2(b[nt], wB + ((b_r + nt * 8) * STRD + b_k + kk * 16) * 2);
#pragma unroll
            for (int mt = 0; mt < MT; mt++)
#pragma unroll
                for (int nt = 0; nt < 4; nt++)
                    mma16816(acc[mt][nt], a[mt], b[nt]);
        }
    }

    const int er = bm + warp_m * (MT * 16) + (lane >> 2);
    const int ec = bn + warp_n * 32 + (lane & 3) * 2;
#pragma unroll
    for (int mt = 0; mt < MT; mt++)
#pragma unroll
        for (int nt = 0; nt < 4; nt++) {
            int r0 = er + mt * 16;
            int r1 = r0 + 8;
            int c = ec + nt * 8;
            float* ac = acc[mt][nt];
            if (EPI == 0) {
                *(float2*)&C[(size_t)r0 * ldC + c] = make_float2(ac[0], ac[1]);
                *(float2*)&C[(size_t)r1 * ldC + c] = make_float2(ac[2], ac[3]);
            } else if (EPI == 1) {
                if (c < Nstore) {
                    *(float2*)&C[(size_t)r0 * ldC + c] = make_float2(ac[0], ac[1]);
                    *(float2*)&C[(size_t)r1 * ldC + c] = make_float2(ac[2], ac[3]);
                }
                if (blockIdx.x == 0) {   // c < 64; pad cols >= 48 with zero
                    __half2 z = __half2(__half(0.f), __half(0.f));
                    __half2 h0 = (c < Rr) ? __floats2half2_rn(ac[0], ac[1]) : z;
                    __half2 h1 = (c < Rr) ? __floats2half2_rn(ac[2], ac[3]) : z;
                    *(__half2*)&aux[(size_t)r0 * 64 + c] = h0;
                    *(__half2*)&aux[(size_t)r1 * 64 + c] = h1;
                }
            } else if (EPI == 2) {
                float u[4] = {ac[0], ac[1], ac[2], ac[3]};
#pragma unroll
                for (int e = 0; e < 4; e++) {
                    int col = c + (e & 1);
                    int row = (e < 2) ? r0 : r1;
                    float v = u[e] + bias[col];
                    v = (v > 15.f) ? v : __logf(1.f + __expf(v));
                    if ((row & (Sl - 1)) == Sl - 1) v *= lastscale[col];
                    u[e] = v;
                }
                *(__half2*)&aux[(size_t)r0 * ldC + c] = __floats2half2_rn(u[0], u[1]);
                *(__half2*)&aux[(size_t)r1 * ldC + c] = __floats2half2_rn(u[2], u[3]);
            } else {  // EPI == 3
                if (c < Iw) {
                    *(__half2*)&aux[(size_t)r0 * Iw + c] = __floats2half2_rn(ac[0], ac[1]);
                    *(__half2*)&aux[(size_t)r1 * Iw + c] = __floats2half2_rn(ac[2], ac[3]);
                } else {
                    int cg = c - Iw;
                    *(__half2*)&aux2[(size_t)r0 * Iw + cg] =
                        __floats2half2_rn(fast_silu(ac[0]), fast_silu(ac[1]));
                    *(__half2*)&aux2[(size_t)r1 * Iw + cg] =
                        __floats2half2_rn(fast_silu(ac[2]), fast_silu(ac[3]));
                }
            }
        }
}

// ---------------------------------------------------------------------------
// Fused prep: all fp32->fp16 conversions in one launch.
// ---------------------------------------------------------------------------
#define PN0 ((Ms * Dm) / 4)
#define PN1 ((TWO_I * Dm) / 4)
#define PN2 ((Dm * Iw) / 4)
#define PN3 ((128 * Iw) / 4)
#define PN4 ((Iw * 64) / 4)
#define PTOT (PN0 + PN1 + PN2 + PN3 + PN4)

__global__ __launch_bounds__(256)
void prep_f16(const float* __restrict__ x, const float* __restrict__ w1f,
              const float* __restrict__ w2f, const float* __restrict__ wxf,
              const float* __restrict__ wdtf,
              __half* __restrict__ x16, __half* __restrict__ w1,
              __half* __restrict__ w2, __half* __restrict__ wx16,
              __half* __restrict__ wdt16)
{
    int i = blockIdx.x * 256 + threadIdx.x;
    if (i >= PTOT) return;
    const float* src;
    __half* dst;
    long j;
    long srcoff;
    bool zero = false;
    if (i < PN0) { j = i; srcoff = j * 4; src = x; dst = x16; }
    else if (i < PN0 + PN1) { j = i - PN0; srcoff = j * 4; src = w1f; dst = w1; }
    else if (i < PN0 + PN1 + PN2) { j = i - PN0 - PN1; srcoff = j * 4; src = w2f; dst = w2; }
    else if (i < PN0 + PN1 + PN2 + PN3) {
        j = i - PN0 - PN1 - PN2; srcoff = j * 4; src = wxf; dst = wx16;
        zero = ((j * 4) / Iw) >= (Rr + 2 * Nst);
    } else {
        j = i - PN0 - PN1 - PN2 - PN3; src = wdtf; dst = wdt16;
        long col4 = j & 15, row = j >> 4;
        zero = (col4 >= 12);
        srcoff = row * Rr + col4 * 4;
    }
    __half2* op = (__half2*)(dst + j * 4);
    if (zero) {
        op[0] = __half2(__half(0.f), __half(0.f));
        op[1] = __half2(__half(0.f), __half(0.f));
    } else {
        float4 v = *(const float4*)(src + srcoff);
        op[0] = __floats2half2_rn(v.x, v.y);
        op[1] = __floats2half2_rn(v.z, v.w);
    }
}

// ---------------------------------------------------------------------------
// Causal depthwise conv1d (K=4) + bias + SiLU — half2 rolling window.
// ---------------------------------------------------------------------------
__global__ __launch_bounds__(256)
void conv_silu3(const __half* __restrict__ hid,
                const float* __restrict__ cw,
                const float* __restrict__ cb,
                __half* __restrict__ h16)
{
    const int blk = blockIdx.x;                 // Bsz * (Sl/16)
    const int b = blk / (Sl / 16);
    const int st = (blk % (Sl / 16)) * 16;
    const int rs = Iw / 2;                      // half2 row stride

#pragma unroll 1
    for (int ic = 0; ic < Iw / 512; ic++) {
        const int p = ic * 256 + threadIdx.x;   // channel pair 0..767
        const int i = p * 2;
        float4 wa = *(const float4*)(cw + (size_t)i * 4);
        float4 wb = *(const float4*)(cw + (size_t)(i + 1) * 4);
        float bx = cb[i], by = cb[i + 1];
        const __half2* base = (const __half2*)(hid + ((size_t)b * Sl + st) * Iw) + p;
        __half2* outp = (__half2*)(h16 + ((size_t)b * Sl + st) * Iw) + p;

        float2 x3, x2, x1;
        if (st > 0) {
            x3 = __half22float2(base[-3 * rs]);
            x2 = __half22float2(base[-2 * rs]);
            x1 = __half22float2(base[-1 * rs]);
        } else {
            x3 = make_float2(0.f, 0.f); x2 = x3; x1 = x3;
        }
#pragma unroll
        for (int s = 0; s < 16; s++) {
            float2 x0 = __half22float2(base[(size_t)s * rs]);
            float ax = fmaf(wa.w, x0.x, fmaf(wa.z, x1.x, fmaf(wa.y, x2.x, fmaf(wa.x, x3.x, bx))));
            float ay = fmaf(wb.w, x0.y, fmaf(wb.z, x1.y, fmaf(wb.y, x2.y, fmaf(wb.x, x3.y, by))));
            ax = fast_silu(ax);
            ay = fast_silu(ay);
            outp[(size_t)s * rs] = __floats2half2_rn(ax, ay);
            x3 = x2; x2 = x1; x1 = x0;
        }
    }
}

// ---------------------------------------------------------------------------
// Selective scan v6: 2 states/lane, 8 lanes/channel, 16 ch/block, 128 threads.
// fp16 dt/h/gate; exp2-domain decay.
// ---------------------------------------------------------------------------
#define SCT 64
#define NCHK (Sl / SCT)
#define LOG2E 1.44269504f

__global__ __launch_bounds__(128)
void scan_kernel6(const __half* __restrict__ dt16,
                  const __half* __restrict__ h16,
                  const float* __restrict__ ssm,
                  const __half* __restrict__ gate16,
                  const float* __restrict__ A_log,
                  const float* __restrict__ Dv,
                  const float* __restrict__ fg,
                  __half* __restrict__ y16)
{
    __shared__ __align__(16) float  s_B [2][SCT][16];
    __shared__ __align__(16) float  s_C [2][SCT][16];
    __shared__ __align__(16) __half s_dt[2][SCT][16];
    __shared__ __align__(16) __half s_h [2][SCT][16];
    __shared__ __align__(16) __half s_g [2][SCT][16];
    __shared__ __align__(16) float  s_y [SCT][16];
    __shared__ float s_D[16];

    const int tid = threadIdx.x;                // 0..127
    const int blk = blockIdx.x;                 // 0..191
    const int b = blk / (Iw / 16);
    const int i0 = (blk % (Iw / 16)) * 16;

    const int wid = tid >> 5;                   // 0..3
    const int lane = tid & 31;
    const int ci = wid * 4 + (lane >> 3);       // channel 0..15
    const int sl = lane & 7;                    // 2 states: sl*2, sl*2+1

    if (tid < 16) s_D[tid] = Dv[i0 + tid];

    // An pre-scaled by log2(e): dA = exp2(An2 * dt)
    float An0 = -__expf(A_log[(size_t)(i0 + ci) * Nst + sl * 2]) * LOG2E;
    float An1 = -__expf(A_log[(size_t)(i0 + ci) * Nst + sl * 2 + 1]) * LOG2E;
    float st0 = 0.f, st1 = 0.f;

    const size_t row0 = (size_t)b * Sl;
    const float fgi = fg[i0 + ci];              // only used via epilogue below

    const uint32_t a_B  = smem_u32(&s_B [0][0][0]);
    const uint32_t a_C  = smem_u32(&s_C [0][0][0]);
    const uint32_t a_dt = smem_u32(&s_dt[0][0][0]);
    const uint32_t a_h  = smem_u32(&s_h [0][0][0]);
    const uint32_t a_g  = smem_u32(&s_g [0][0][0]);
    const uint32_t stoff  = SCT * 16 * 4;
    const uint32_t stoffh = SCT * 16 * 2;

    auto issue = [&](int st, int s0) {
#pragma unroll
        for (int l = 0; l < 2; l++) {
            int v = tid + l * 128;
            int r = v >> 2, c4 = (v & 3) * 4;
            size_t grow = row0 + s0 + r;
            uint32_t off = st * stoff + (r * 16 + c4) * 4;
            cp16(a_B + off, ssm + grow * (Rr + 2 * Nst) + Rr + c4);
            cp16(a_C + off, ssm + grow * (Rr + 2 * Nst) + Rr + Nst + c4);
        }
        {
            int v = tid;
            int r = v >> 1, c8 = (v & 1) * 8;
            size_t grow = row0 + s0 + r;
            uint32_t offh = st * stoffh + (r * 16 + c8) * 2;
            cp16(a_dt + offh, dt16   + grow * Iw + i0 + c8);
            cp16(a_h  + offh, h16    + grow * Iw + i0 + c8);
            cp16(a_g  + offh, gate16 + grow * Iw + i0 + c8);
        }
        CP_COMMIT();
    };

    issue(0, 0);

    for (int ch = 0; ch < NCHK; ch++) {
        const int st = ch & 1;
        const int s0 = ch * SCT;
        if (ch + 1 < NCHK) { issue(st ^ 1, s0 + SCT); CP_WAIT(1); }
        else               { CP_WAIT(0); }
        __syncthreads();

#pragma unroll 4
        for (int s = 0; s < SCT; s++) {
            float dtv = __half2float(s_dt[st][s][ci]);
            float hv  = __half2float(s_h [st][s][ci]);
            float2 Bv = *(const float2*)&s_B[st][s][sl * 2];
            float2 Cv = *(const float2*)&s_C[st][s][sl * 2];
            float dth = dtv * hv;
            st0 = fmaf(exp2f(An0 * dtv), st0, dth * Bv.x);
            st1 = fmaf(exp2f(An1 * dtv), st1, dth * Bv.y);
            float part = st0 * Cv.x + st1 * Cv.y;
            part += __shfl_xor_sync(0xffffffffu, part, 4);
            part += __shfl_xor_sync(0xffffffffu, part, 2);
            part += __shfl_xor_sync(0xffffffffu, part, 1);
            if (sl == 0) s_y[s][ci] = part;
        }
        __syncthreads();

#pragma unroll
        for (int k = 0; k < 8; k++) {
            int idx = tid + k * 128;
            int r = idx >> 4, c = idx & 15;
            float hv = __half2float(s_h[st][r][c]);
            float sg = __half2float(s_g[st][r][c]);
            float val = (s_y[r][c] + hv * s_D[c]) * sg;
            if (s0 + r == Sl - 1) val *= fg[i0 + c];
            y16[(row0 + s0 + r) * Iw + i0 + c] = __float2half_rn(val);
        }
        __syncthreads();
    }
    (void)fgi;
}

// ---------------------------------------------------------------------------
// Launch
// ---------------------------------------------------------------------------
extern "C" void kernel_launch(void* const* d_in, const int* in_sizes, int n_in,
                              void* d_out, int out_size)
{
    const float* x          = (const float*)d_in[0];
    const float* in_proj_w  = (const float*)d_in[1];
    const float* conv_w     = (const float*)d_in[2];
    const float* conv_b     = (const float*)d_in[3];
    const float* x_proj_w   = (const float*)d_in[4];
    const float* dt_proj_w  = (const float*)d_in[5];
    const float* dt_proj_b  = (const float*)d_in[6];
    const float* A_log      = (const float*)d_in[7];
    const float* Dv         = (const float*)d_in[8];
    const float* out_proj_w = (const float*)d_in[9];
    const float* alpha      = (const float*)d_in[10];
    const float* fg         = (const float*)d_in[11];
    float* out = (float*)d_out;

    float* ssm;
    cudaGetSymbolAddress((void**)&ssm, g_ssm);

    __half *x16, *w1, *hid16, *gate16, *h16, *wx16, *ts16, *wdt16, *dt16, *y16, *w2;
    cudaGetSymbolAddress((void**)&x16,    g_x16);
    cudaGetSymbolAddress((void**)&w1,     g_w1);
    cudaGetSymbolAddress((void**)&hid16,  g_hid16);
    cudaGetSymbolAddress((void**)&gate16, g_gate16);
    cudaGetSymbolAddress((void**)&h16,    g_h16);
    cudaGetSymbolAddress((void**)&wx16,   g_wx16);
    cudaGetSymbolAddress((void**)&ts16,   g_ts16);
    cudaGetSymbolAddress((void**)&wdt16,  g_wdt16);
    cudaGetSymbolAddress((void**)&dt16,   g_dt16);
    cudaGetSymbolAddress((void**)&y16,    g_y16);
    cudaGetSymbolAddress((void**)&w2,     g_w2);

    constexpr int SMEM_BIG   = 3 * (128 + 128) * STRD * 2;   // 61440
    constexpr int SMEM_MED   = 3 * (128 + 64) * STRD * 2;    // 46080
    constexpr int SMEM_SMALL = 3 * (64 + 64) * STRD * 2;     // 30720
    cudaFuncSetAttribute(hmma_f16<128,128,3>, cudaFuncAttributeMaxDynamicSharedMemorySize, SMEM_BIG);
    cudaFuncSetAttribute(hmma_f16<64,64,1>,   cudaFuncAttributeMaxDynamicSharedMemorySize, SMEM_SMALL);
    cudaFuncSetAttribute(hmma_f16<128,64,2>,  cudaFuncAttributeMaxDynamicSharedMemorySize, SMEM_MED);
    cudaFuncSetAttribute(hmma_f16<128,64,0>,  cudaFuncAttributeMaxDynamicSharedMemorySize, SMEM_MED);

    // 0) all fp16 conversions in one launch
    prep_f16<<<(PTOT + 255) / 256, 256>>>(x, in_proj_w, out_proj_w, x_proj_w,
                                          dt_proj_w, x16, w1, w2, wx16, wdt16);

    // 1) in_proj (EPI=3): hidden -> hid16, silu(gate) -> gate16
    hmma_f16<128,128,3><<<dim3(TWO_I / 128, Ms / 128), 256, SMEM_BIG>>>(
        x16, w1, nullptr, Ms, Dm, TWO_I, TWO_I, nullptr, nullptr, hid16, gate16);

    // 2) conv + SiLU -> h16
    conv_silu3<<<Bsz * (Sl / 16), 256>>>(hid16, conv_w, conv_b, h16);

    // 3) x_proj (BM=64, EPI=1): ssm fp32 (cols<80) + ts16 fp16 padded
    hmma_f16<64,64,1><<<dim3(2, Ms / 64), 256, SMEM_SMALL>>>(
        h16, wx16, ssm, Ms, Iw, Rr + 2 * Nst, Rr + 2 * Nst, nullptr, nullptr, ts16, nullptr);

    // 4) dt_proj (BM=128, BN=64, EPI=2): dt16 = softplus(ts16 @ wdt16^T + b)
    hmma_f16<128,64,2><<<dim3(Iw / 64, Ms / 128), 256, SMEM_MED>>>(
        ts16, wdt16, nullptr, Ms, 64, Iw, Iw, dt_proj_b, alpha, dt16, nullptr);

    // 5) scan v6 (fp16 dt/h/gate, emits fp16 y)
    scan_kernel6<<<(Bsz * Iw) / 16, 128>>>(dt16, h16, ssm, gate16, A_log, Dv, fg, y16);

    // 6) out_proj (BM=128, BN=64, EPI=0): out[4096,768] = y16 @ w2^T
    hmma_f16<128,64,0><<<dim3(Dm / 64, Ms / 128), 256, SMEM_MED>>>(
        y16, w2, out, Ms, Iw, Dm, Dm, nullptr, nullptr, nullptr, nullptr);
}